// round 10
// baseline (speedup 1.0000x reference)
#include <cuda_runtime.h>
#include <cuda_bf16.h>
#include <math.h>
#include <cstdint>

#define BB 256
#define SS 4096
#define HH 64
#define GG 192   // 3*H
#define RB 8     // batches per rec CTA

// Scratch
__device__ float g_buf[(size_t)BB * SS * HH];      // 268 MB  layer activations
__device__ float g_xi [(size_t)BB * SS * GG];      // 805 MB  xi incl. b_ih, layout [b][t][row]
__device__ float g_scores[(size_t)BB * 4 * SS];    // 16 MB

__device__ __forceinline__ float sigmoidf_(float x) {
    return 1.0f / (1.0f + __expf(-x));
}
__device__ __forceinline__ float tanhf_(float x) {
    x = fminf(fmaxf(x, -15.0f), 15.0f);
    float e = __expf(2.0f * x);
    return (e - 1.0f) / (e + 1.0f);
}

// ---- tf32 helpers (xi gemm, verified R7) ----
__device__ __forceinline__ uint32_t f2tf32_(float x) {
    uint32_t r;
    asm("cvt.rna.tf32.f32 %0, %1;" : "=r"(r) : "f"(x));
    return r;
}
__device__ __forceinline__ void mma_tf32_(float* c, const uint32_t* a, const uint32_t* b) {
    asm volatile("mma.sync.aligned.m16n8k8.row.col.f32.tf32.tf32.f32 "
        "{%0,%1,%2,%3},{%4,%5,%6,%7},{%8,%9},{%0,%1,%2,%3};"
        : "+f"(c[0]), "+f"(c[1]), "+f"(c[2]), "+f"(c[3])
        : "r"(a[0]), "r"(a[1]), "r"(a[2]), "r"(a[3]), "r"(b[0]), "r"(b[1]));
}

// ---- bf16 m16n8k16 mma (recurrence) ----
__device__ __forceinline__ void mma_bf16_(float* c, const uint32_t* a, const uint32_t* b) {
    asm volatile("mma.sync.aligned.m16n8k16.row.col.f32.bf16.bf16.f32 "
        "{%0,%1,%2,%3},{%4,%5,%6,%7},{%8,%9},{%0,%1,%2,%3};"
        : "+f"(c[0]), "+f"(c[1]), "+f"(c[2]), "+f"(c[3])
        : "r"(a[0]), "r"(a[1]), "r"(a[2]), "r"(a[3]), "r"(b[0]), "r"(b[1]));
}
__device__ __forceinline__ uint32_t packbf_(float lo, float hi) {
    __nv_bfloat16 l = __float2bfloat16(lo), h = __float2bfloat16(hi);
    return (uint32_t)__bfloat16_as_ushort(l) | ((uint32_t)__bfloat16_as_ushort(h) << 16);
}

// ---------------------------------------------------------------------------
// xi0: g_xi[b][t][row] = wih0[row]*x[b][t] + bih0[row]
// ---------------------------------------------------------------------------
__global__ __launch_bounds__(GG)
void xi0_kernel(const float* __restrict__ x,
                const float* __restrict__ wih0, const float* __restrict__ bih0)
{
    __shared__ float xs[16];
    const int j = threadIdx.x;
    const int t0 = blockIdx.x * 16;
    const int b = blockIdx.y;
    if (j < 16) xs[j] = x[(size_t)b * SS + t0 + j];
    const float w = wih0[j], bi = bih0[j];
    __syncthreads();
    float* outp = g_xi + ((size_t)b * SS + t0) * GG + j;
#pragma unroll
    for (int tt = 0; tt < 16; tt++)
        outp[(size_t)tt * GG] = fmaf(w, xs[tt], bi);
}

// ---------------------------------------------------------------------------
// mma recurrence: one CTA = 8 batches, 12 warps (warp w owns gate rows
// [16w,16w+16)). Per step: C[192x8] = Whh_bf16hi/lo x h_bf16hi/lo (3 terms,
// fp32 accum). Gate warps (rows<128) sigmoid -> srz smem; n-warps combine,
// update h (kept in regs), re-pack h as bf16 hi/lo into smem for next step.
// xi[t] staged in double-buffered smem, prefetched 2 steps ahead.
// ---------------------------------------------------------------------------
__global__ __launch_bounds__(384, 1)
void rec8_kernel(const float* __restrict__ whh, const float* __restrict__ bhh)
{
    __shared__ uint32_t shh[32][8], shl[32][8];   // packed bf16 pairs of h (hi, lo)
    __shared__ float srz[128][8];
    __shared__ float sxi[2][RB][196];             // padded rows: conflict-free reads

    const int tid = threadIdx.x;
    const int wid = tid >> 5, lane = tid & 31;
    const int g = lane >> 2, q = lane & 3;
    const int row0 = wid * 16 + g, row1 = row0 + 8;
    const bool isN = (wid >= 8);
    const int b0c = blockIdx.x * RB;
    const int bb = tid / 48, f4 = (tid % 48) * 4;

    // ---- W_hh fragments (bf16 hi/lo), rows row0/row1, K=64 ----
    uint32_t wfh[4][4], wfl[4][4];
#pragma unroll
    for (int kt = 0; kt < 4; kt++) {
#pragma unroll
        for (int e = 0; e < 4; e++) {
            int rr = wid * 16 + g + (e & 1) * 8;
            int cc = kt * 16 + 2 * q + (e >> 1) * 8;
            float v0 = whh[rr * HH + cc], v1 = whh[rr * HH + cc + 1];
            __nv_bfloat16 h0 = __float2bfloat16(v0), h1 = __float2bfloat16(v1);
            wfh[kt][e] = (uint32_t)__bfloat16_as_ushort(h0) |
                         ((uint32_t)__bfloat16_as_ushort(h1) << 16);
            wfl[kt][e] = packbf_(v0 - __bfloat162float(h0), v1 - __bfloat162float(h1));
        }
    }
    const float bh0 = bhh[row0], bh1 = bhh[row1];

    // zero h smem
    if (tid < 256) { ((uint32_t*)shh)[tid] = 0u; ((uint32_t*)shl)[tid] = 0u; }

    // initial xi prefetch (t=0,1)
    {
        const float* src = g_xi + ((size_t)(b0c + bb) * SS) * GG + f4;
        *(float4*)&sxi[0][bb][f4] = *(const float4*)src;
        *(float4*)&sxi[1][bb][f4] = *(const float4*)(src + GG);
    }
    __syncthreads();

    float hold[4] = {0.f, 0.f, 0.f, 0.f};
    const int kk0 = (wid - 8) * 16 + g;            // n-warps: h indices
    const int kk1 = kk0 + 8;

    for (int t = 0; t < SS; t++) {
        const int buf = t & 1;

        // ---- B fragments from packed h smem ----
        uint32_t bfh[4][2], bfl[4][2];
#pragma unroll
        for (int kt = 0; kt < 4; kt++) {
            bfh[kt][0] = shh[kt * 8 + q][g];
            bfh[kt][1] = shh[kt * 8 + q + 4][g];
            bfl[kt][0] = shl[kt * 8 + q][g];
            bfl[kt][1] = shl[kt * 8 + q + 4][g];
        }

        // ---- 3-term mma (independent accumulator chains) ----
        float ca[4] = {0,0,0,0}, cb[4] = {0,0,0,0}, cc4[4] = {0,0,0,0};
#pragma unroll
        for (int kt = 0; kt < 4; kt++) mma_bf16_(ca, wfh[kt], bfh[kt]);
#pragma unroll
        for (int kt = 0; kt < 4; kt++) mma_bf16_(cb, wfl[kt], bfh[kt]);
#pragma unroll
        for (int kt = 0; kt < 4; kt++) mma_bf16_(cc4, wfh[kt], bfl[kt]);
        const float c0 = ca[0] + cb[0] + cc4[0];
        const float c1 = ca[1] + cb[1] + cc4[1];
        const float c2 = ca[2] + cb[2] + cc4[2];
        const float c3 = ca[3] + cb[3] + cc4[3];

        // ---- xi for my (row, batch) cells ----
        const float xi00 = sxi[buf][2 * q    ][row0];
        const float xi01 = sxi[buf][2 * q + 1][row0];
        const float xi10 = sxi[buf][2 * q    ][row1];
        const float xi11 = sxi[buf][2 * q + 1][row1];

        // ---- prefetch xi[t+2] into regs ----
        float4 pf = make_float4(0.f, 0.f, 0.f, 0.f);
        if (t + 2 < SS)
            pf = *(const float4*)(g_xi + ((size_t)(b0c + bb) * SS + (t + 2)) * GG + f4);

        if (!isN) {
            srz[row0][2 * q    ] = sigmoidf_(c0 + bh0 + xi00);
            srz[row0][2 * q + 1] = sigmoidf_(c1 + bh0 + xi01);
            srz[row1][2 * q    ] = sigmoidf_(c2 + bh1 + xi10);
            srz[row1][2 * q + 1] = sigmoidf_(c3 + bh1 + xi11);
        }
        __syncthreads();   // BAR_A: srz ready; all xi[t]/h reads done

        if (t + 2 < SS) *(float4*)&sxi[buf][bb][f4] = pf;

        if (isN) {
            const float hn0 = c0 + bh0, hn1 = c1 + bh0;
            const float hn2 = c2 + bh1, hn3 = c3 + bh1;
            const float r0 = srz[kk0][2 * q], r1 = srz[kk0][2 * q + 1];
            const float r2 = srz[kk1][2 * q], r3 = srz[kk1][2 * q + 1];
            const float z0 = srz[64 + kk0][2 * q], z1 = srz[64 + kk0][2 * q + 1];
            const float z2 = srz[64 + kk1][2 * q], z3 = srz[64 + kk1][2 * q + 1];
            const float n0 = tanhf_(fmaf(r0, hn0, xi00));
            const float n1 = tanhf_(fmaf(r1, hn1, xi01));
            const float n2 = tanhf_(fmaf(r2, hn2, xi10));
            const float n3 = tanhf_(fmaf(r3, hn3, xi11));
            const float h0n = fmaf(z0, hold[0] - n0, n0);
            const float h1n = fmaf(z1, hold[1] - n1, n1);
            const float h2n = fmaf(z2, hold[2] - n2, n2);
            const float h3n = fmaf(z3, hold[3] - n3, n3);
            hold[0] = h0n; hold[1] = h1n; hold[2] = h2n; hold[3] = h3n;

            // write activations (scattered STG.32, latency-hidden)
            g_buf[((size_t)(b0c + 2 * q    ) * SS + t) * HH + kk0] = h0n;
            g_buf[((size_t)(b0c + 2 * q + 1) * SS + t) * HH + kk0] = h1n;
            g_buf[((size_t)(b0c + 2 * q    ) * SS + t) * HH + kk1] = h2n;
            g_buf[((size_t)(b0c + 2 * q + 1) * SS + t) * HH + kk1] = h3n;

            // bf16 hi/lo split + pair with k-partner (g^1 <-> lane^4)
            uint32_t pk[4];
#pragma unroll
            for (int s = 0; s < 4; s++) {
                float v = hold[s];
                __nv_bfloat16 hb = __float2bfloat16(v);
                float lof = v - __bfloat162float(hb);
                __nv_bfloat16 lb = __float2bfloat16(lof);
                pk[s] = (uint32_t)__bfloat16_as_ushort(hb) |
                        ((uint32_t)__bfloat16_as_ushort(lb) << 16);
            }
            uint32_t pr[4];
#pragma unroll
            for (int s = 0; s < 4; s++)
                pr[s] = __shfl_xor_sync(0xFFFFFFFFu, pk[s], 4);
            if ((g & 1) == 0) {
                const int kp0 = kk0 >> 1;          // = 8*(wid-8)*2... (16i+g)/2, g even
                const int kp1 = kk1 >> 1;
                // hi words: low16 of pk/pr; lo words: high16
                shh[kp0][2 * q    ] = (pk[0] & 0xFFFFu) | ((pr[0] & 0xFFFFu) << 16);
                shh[kp0][2 * q + 1] = (pk[1] & 0xFFFFu) | ((pr[1] & 0xFFFFu) << 16);
                shh[kp1][2 * q    ] = (pk[2] & 0xFFFFu) | ((pr[2] & 0xFFFFu) << 16);
                shh[kp1][2 * q + 1] = (pk[3] & 0xFFFFu) | ((pr[3] & 0xFFFFu) << 16);
                shl[kp0][2 * q    ] = (pk[0] >> 16) | (pr[0] & 0xFFFF0000u);
                shl[kp0][2 * q + 1] = (pk[1] >> 16) | (pr[1] & 0xFFFF0000u);
                shl[kp1][2 * q    ] = (pk[2] >> 16) | (pr[2] & 0xFFFF0000u);
                shl[kp1][2 * q + 1] = (pk[3] >> 16) | (pr[3] & 0xFFFF0000u);
            }
        }
        __syncthreads();   // BAR_B: new h visible
    }
}

// ---------------------------------------------------------------------------
// xi GEMM on mma.sync tf32 (hi/lo, fp32 accum) — verified in R7 (679us).
// ---------------------------------------------------------------------------
__global__ __launch_bounds__(512, 1)
void xi_gemm_mma(const float* __restrict__ wih, const float* __restrict__ bih)
{
    __shared__ __align__(16) float sA[128 * 68];

    const int tid = threadIdx.x;
    const int wid = tid >> 5, lane = tid & 31;
    const int wm = wid & 3, wn = wid >> 2;
    const int g = lane >> 2, q = lane & 3;
    const size_t row0 = (size_t)blockIdx.x * 128;

    {
        const float4* src = (const float4*)(g_buf + row0 * HH);
#pragma unroll
        for (int i = 0; i < 4; i++) {
            int idx = tid + i * 512;
            int rr = idx >> 4, c4 = idx & 15;
            float4 v = src[idx];
            *(float4*)(sA + rr * 68 + c4 * 4) = v;
        }
    }
    __syncthreads();

    float c[2][6][4] = {};

    for (int kt = 0; kt < 8; kt++) {
        uint32_t ah[2][4], al[2][4];
#pragma unroll
        for (int mt = 0; mt < 2; mt++) {
#pragma unroll
            for (int e = 0; e < 4; e++) {
                int row = wm * 32 + mt * 16 + g + (e & 1) * 8;
                int col = kt * 8 + q + (e >> 1) * 4;
                float v = sA[row * 68 + col];
                uint32_t hi = f2tf32_(v);
                ah[mt][e] = hi;
                al[mt][e] = f2tf32_(v - __uint_as_float(hi));
            }
        }
        uint32_t bh[6][2], bl[6][2];
#pragma unroll
        for (int nt = 0; nt < 6; nt++) {
#pragma unroll
            for (int e = 0; e < 2; e++) {
                int n = wn * 48 + nt * 8 + g;
                int k = kt * 8 + q + e * 4;
                float v = __ldg(&wih[n * 64 + k]);
                uint32_t hi = f2tf32_(v);
                bh[nt][e] = hi;
                bl[nt][e] = f2tf32_(v - __uint_as_float(hi));
            }
        }
#pragma unroll
        for (int mt = 0; mt < 2; mt++) {
#pragma unroll
            for (int nt = 0; nt < 6; nt++) {
                mma_tf32_(c[mt][nt], ah[mt], bh[nt]);
                mma_tf32_(c[mt][nt], al[mt], bh[nt]);
                mma_tf32_(c[mt][nt], ah[mt], bl[nt]);
            }
        }
    }

#pragma unroll
    for (int mt = 0; mt < 2; mt++) {
        const size_t row = row0 + wm * 32 + mt * 16 + g;
#pragma unroll
        for (int nt = 0; nt < 6; nt++) {
            const int col = wn * 48 + nt * 8 + q * 2;
            const float b0v = __ldg(&bih[col]);
            const float b1v = __ldg(&bih[col + 1]);
            *(float2*)(g_xi + row * GG + col) =
                make_float2(c[mt][nt][0] + b0v, c[mt][nt][1] + b1v);
            *(float2*)(g_xi + (row + 8) * GG + col) =
                make_float2(c[mt][nt][2] + b0v, c[mt][nt][3] + b1v);
        }
    }
}

// ---------------------------------------------------------------------------
// Attention + head (unchanged; known-good).
// ---------------------------------------------------------------------------
__global__ __launch_bounds__(256)
void attn_kernel(
    const float* __restrict__ in_proj_w, const float* __restrict__ in_proj_b,
    const float* __restrict__ out_proj_w, const float* __restrict__ out_proj_b,
    const float* __restrict__ fc_w, const float* __restrict__ fc_b,
    float* __restrict__ out)
{
    const int b = blockIdx.x;
    const int tid = threadIdx.x;

    __shared__ __align__(16) float shl2[HH];
    __shared__ __align__(16) float sq[HH];
    __shared__ __align__(16) float sg[4][HH];
    __shared__ float sc[4];
    __shared__ float sred[4][256];
    __shared__ float sm4[4], sl4[4];
    __shared__ __align__(16) float stile[64][HH];
    __shared__ float sw[4][64];
    __shared__ float su[4][HH];
    __shared__ __align__(16) float sctx[HH];
    __shared__ float sao[HH];

    const float* mybuf = g_buf + (size_t)b * SS * HH;

    if (tid < HH) shl2[tid] = mybuf[(size_t)(SS - 1) * HH + tid];
    __syncthreads();

    if (tid < HH) {
        float acc = in_proj_b[tid];
#pragma unroll
        for (int k = 0; k < HH; k++)
            acc = fmaf(in_proj_w[tid * HH + k], shl2[k], acc);
        sq[tid] = acc;
    }
    __syncthreads();

    if (tid < HH) {
#pragma unroll
        for (int h = 0; h < 4; h++) {
            float acc = 0.0f;
#pragma unroll
            for (int d = 0; d < 16; d++)
                acc = fmaf(sq[h * 16 + d], in_proj_w[(HH + h * 16 + d) * HH + tid], acc);
            sg[h][tid] = acc * 0.25f;
        }
    }
    if (tid < 4) {
        float acc = 0.0f;
#pragma unroll
        for (int d = 0; d < 16; d++)
            acc = fmaf(sq[tid * 16 + d], in_proj_b[HH + tid * 16 + d], acc);
        sc[tid] = acc * 0.25f;
    }
    __syncthreads();

    float mloc[4] = {-1e30f, -1e30f, -1e30f, -1e30f};
    for (int s = tid; s < SS; s += 256) {
        const float4* ov = (const float4*)(mybuf + (size_t)s * HH);
        float4 o[16];
#pragma unroll
        for (int kk = 0; kk < 16; kk++) o[kk] = ov[kk];
#pragma unroll
        for (int h = 0; h < 4; h++) {
            const float4* gv = (const float4*)sg[h];
            float a0 = sc[h], a1 = 0.f, a2 = 0.f, a3 = 0.f;
#pragma unroll
            for (int kk = 0; kk < 16; kk++) {
                float4 g4 = gv[kk];
                a0 = fmaf(g4.x, o[kk].x, a0);
                a1 = fmaf(g4.y, o[kk].y, a1);
                a2 = fmaf(g4.z, o[kk].z, a2);
                a3 = fmaf(g4.w, o[kk].w, a3);
            }
            float sv = (a0 + a1) + (a2 + a3);
            g_scores[((size_t)(b * 4 + h)) * SS + s] = sv;
            mloc[h] = fmaxf(mloc[h], sv);
        }
    }
#pragma unroll
    for (int h = 0; h < 4; h++) sred[h][tid] = mloc[h];
    __syncthreads();
    if (tid < 4) {
        float m = -1e30f;
        for (int i = 0; i < 256; i++) m = fmaxf(m, sred[tid][i]);
        sm4[tid] = m;
    }
    __syncthreads();

    const int h = tid >> 6;
    const int e = tid & 63;
    const float mh = sm4[h];
    float uacc = 0.0f, lloc = 0.0f;

    for (int tile = 0; tile < SS / 64; tile++) {
        const int s0 = tile * 64;
        {
            float4* st4 = (float4*)stile;
            const float4* gv = (const float4*)(mybuf + (size_t)s0 * HH);
#pragma unroll
            for (int r = 0; r < 4; r++) {
                int idx = tid + r * 256;
                st4[idx] = gv[idx];
            }
        }
        {
            float w = __expf(g_scores[((size_t)(b * 4 + h)) * SS + s0 + e] - mh);
            sw[h][e] = w;
            lloc += w;
        }
        __syncthreads();
#pragma unroll
        for (int sp = 0; sp < 64; sp++)
            uacc = fmaf(sw[h][sp], stile[sp][e], uacc);
        __syncthreads();
    }

    ((float*)sred)[tid] = lloc;
    __syncthreads();
    if (tid < 4) {
        float l = 0.0f;
        for (int i = 0; i < 64; i++) l += ((float*)sred)[tid * 64 + i];
        sl4[tid] = l;
    }
    __syncthreads();

    su[h][e] = uacc / sl4[h];
    __syncthreads();

    if (tid < HH) {
        const int hh = tid >> 4;
        float acc = in_proj_b[128 + tid];
#pragma unroll
        for (int k = 0; k < HH; k++)
            acc = fmaf(in_proj_w[(128 + tid) * HH + k], su[hh][k], acc);
        sctx[tid] = acc;
    }
    __syncthreads();

    if (tid < HH) {
        float acc = out_proj_b[tid];
#pragma unroll
        for (int k = 0; k < HH; k++)
            acc = fmaf(out_proj_w[tid * HH + k], sctx[k], acc);
        sao[tid] = fc_w[tid] * acc;
    }
    __syncthreads();

    if (tid == 0) {
        float lg = fc_b[0];
        for (int i = 0; i < HH; i++) lg += sao[i];
        out[b] = 1.0f / (1.0f + __expf(-lg));
    }
}

// ---------------------------------------------------------------------------
extern "C" void kernel_launch(void* const* d_in, const int* in_sizes, int n_in,
                              void* d_out, int out_size)
{
    const float* x    = (const float*)d_in[0];
    const float* wih0 = (const float*)d_in[1];
    const float* whh0 = (const float*)d_in[2];
    const float* bih0 = (const float*)d_in[3];
    const float* bhh0 = (const float*)d_in[4];
    const float* wih1 = (const float*)d_in[5];
    const float* whh1 = (const float*)d_in[6];
    const float* bih1 = (const float*)d_in[7];
    const float* bhh1 = (const float*)d_in[8];
    const float* wih2 = (const float*)d_in[9];
    const float* whh2 = (const float*)d_in[10];
    const float* bih2 = (const float*)d_in[11];
    const float* bhh2 = (const float*)d_in[12];
    const float* ipw  = (const float*)d_in[13];
    const float* ipb  = (const float*)d_in[14];
    const float* opw  = (const float*)d_in[15];
    const float* opb  = (const float*)d_in[16];
    const float* fcw  = (const float*)d_in[17];
    const float* fcb  = (const float*)d_in[18];

    xi0_kernel<<<dim3(SS / 16, BB), GG>>>(x, wih0, bih0);   // #1
    rec8_kernel<<<BB / RB, 384>>>(whh0, bhh0);              // #2  layer 0
    xi_gemm_mma<<<8192, 512>>>(wih1, bih1);                 // #3
    rec8_kernel<<<BB / RB, 384>>>(whh1, bhh1);              // #4  layer 1 (profiled)
    xi_gemm_mma<<<8192, 512>>>(wih2, bih2);                 // #5
    rec8_kernel<<<BB / RB, 384>>>(whh2, bhh2);              // #6  layer 2
    attn_kernel<<<BB, 256>>>(ipw, ipb, opw, opb, fcw, fcb, (float*)d_out);
}